// round 11
// baseline (speedup 1.0000x reference)
#include <cuda_runtime.h>
#include <cstdint>

// Attention_18021682774359: BiDAF-style context-query attention.
// B=64, CL=400, QL=50, H=1024. Output [B, CL, 4H] fp32.
//
// Round 11: soft2 split into two 512-block phases (slab-parallel online
// softmax over c; coalesced reads, full-chip occupancy). K1 split-K=2
// reinstated (partials cheap to sum in the new slab-structured softmaxes).

namespace {
constexpr int B_  = 64;
constexpr int CL_ = 400;
constexpr int QL_ = 50;
constexpr int H_  = 1024;
constexpr int QS_ = 64;   // padded QL
}

// -------- scratch (device globals; allocation-free) --------
__device__ float g_G    [B_*CL_*QS_];   // K1 partial (z=0)
__device__ float g_G2   [B_*CL_*QS_];   // K1 partial (z=1)
__device__ float g_s1   [B_*CL_*QS_];
__device__ float g_s2   [B_*CL_*QS_];
__device__ float g_qpad [B_*QS_*H_];    // raw q, zero-padded rows
__device__ float g_qpadw[B_*QS_*H_];    // q * cqw, zero-padded rows
__device__ float g_t    [B_*QS_*H_];
__device__ float g_cdot [B_*CL_];       // partial (z=0)
__device__ float g_cdot2[B_*CL_];       // partial (z=1)
__device__ float g_qdot [B_*QS_];
__device__ float g_pM   [B_*8*QS_];     // soft2 slab partial max
__device__ float g_pS   [B_*8*QS_];     // soft2 slab partial sum

__device__ __forceinline__ unsigned smem_u32(const void* p) {
    return (unsigned)__cvta_generic_to_shared(p);
}
__device__ __forceinline__ void cp_async16(unsigned dst, const void* src, bool pred) {
    int sz = pred ? 16 : 0;
    asm volatile("cp.async.cg.shared.global [%0], [%1], 16, %2;"
                 :: "r"(dst), "l"(src), "r"(sz) : "memory");
}
__device__ __forceinline__ void cp_commit() {
    asm volatile("cp.async.commit_group;" ::: "memory");
}

// ============================================================
// K0: zero-padded q copies + fused qdot (block == one (b,j) row)
// ============================================================
__global__ __launch_bounds__(256) void k_qpad(
    const float* __restrict__ q, const float* __restrict__ cqw,
    const float* __restrict__ qw)
{
    __shared__ float red[8];
    int blk = blockIdx.x;            // b*64 + j
    int j = blk & 63, b = blk >> 6;
    int h4 = threadIdx.x;            // 0..255 float4 position
    float4 v = make_float4(0.f, 0.f, 0.f, 0.f);
    if (j < QL_) v = ((const float4*)q)[((b * QL_ + j) << 8) + h4];
    int idx = (blk << 8) + h4;
    ((float4*)g_qpad)[idx] = v;
    float4 w = ((const float4*)cqw)[h4];
    ((float4*)g_qpadw)[idx] = make_float4(v.x*w.x, v.y*w.y, v.z*w.z, v.w*w.w);

    float4 ww = ((const float4*)qw)[h4];
    float s = v.x*ww.x + v.y*ww.y + v.z*ww.z + v.w*ww.w;
#pragma unroll
    for (int o = 16; o; o >>= 1) s += __shfl_xor_sync(0xffffffffu, s, o);
    int lane = threadIdx.x & 31, wid = threadIdx.x >> 5;
    if (lane == 0) red[wid] = s;
    __syncthreads();
    if (threadIdx.x == 0) {
        float t = 0.f;
#pragma unroll
        for (int r = 0; r < 8; r++) t += red[r];
        g_qdot[blk] = t;
    }
}

// ============================================================
// K1: G[b, i-tile 64, j 64] = c @ qpadw^T, split-K=2 (z over K halves).
// 64 threads, micro 8x8, k-vectorized, crosswise swizzle, cp.async.
// Fused: tx==0 lanes accumulate cdot = c . cw from the resident A-tile.
// ============================================================
__global__ __launch_bounds__(64, 6) void k_simgemm(
    const float* __restrict__ c, const float* __restrict__ cw)
{
    __shared__ float4 As4[2][512];   // 64 rows x 8 kgroups
    __shared__ float4 Bs4[2][512];
    __shared__ float4 CwS[2][8];
    int b  = blockIdx.y;
    int i0 = blockIdx.x * 64;
    int z  = blockIdx.z;             // K half: chunks [z*16, z*16+16)
    int tid = threadIdx.x, tx = tid & 7, ty = tid >> 3;
    const float* cb = c        + (size_t)b * CL_ * H_;
    const float* qb = g_qpadw  + (size_t)b * QS_ * H_;

    float acc[8][8];
#pragma unroll
    for (int i = 0; i < 8; i++)
#pragma unroll
        for (int j = 0; j < 8; j++) acc[i][j] = 0.f;
    float cd[8];
#pragma unroll
    for (int i = 0; i < 8; i++) cd[i] = 0.f;

    auto stage = [&](int ch, int buf) {
        int kc = (z * 16 + ch) * 32;
#pragma unroll
        for (int u = 0; u < 8; u++) {
            int idx = tid + 64 * u;
            int m = idx >> 3, kg = idx & 7;
            bool p = (i0 + m) < CL_;
            const float* src = cb + (size_t)(p ? (i0 + m) : 0) * H_ + kc + kg * 4;
            cp_async16(smem_u32(&As4[buf][m * 8 + (kg ^ ((m >> 2) & 7))]), src, p);
        }
#pragma unroll
        for (int u = 0; u < 8; u++) {
            int idx = tid + 64 * u;
            int n = idx >> 3, kg = idx & 7;
            cp_async16(smem_u32(&Bs4[buf][n * 8 + (kg ^ ((n >> 2) & 7))]),
                       qb + (size_t)n * H_ + kc + kg * 4, true);
        }
        if (tid < 8) cp_async16(smem_u32(&CwS[buf][tid]), cw + kc + tid * 4, true);
        cp_commit();
    };

    stage(0, 0);
    for (int ch = 0; ch < 16; ch++) {
        int buf = ch & 1;
        if (ch < 15) {
            stage(ch + 1, buf ^ 1);
            asm volatile("cp.async.wait_group 1;" ::: "memory");
        } else {
            asm volatile("cp.async.wait_group 0;" ::: "memory");
        }
        __syncthreads();
#pragma unroll 1
        for (int kg = 0; kg < 8; kg++) {
            float4 a4[8], b4[8];
#pragma unroll
            for (int ii = 0; ii < 4; ii++) {
                a4[ii]     = As4[buf][(ty * 4 + ii)      * 8 + (kg ^ ty)];
                a4[ii + 4] = As4[buf][(ty * 4 + 32 + ii) * 8 + (kg ^ ty)];
                b4[ii]     = Bs4[buf][(tx * 4 + ii)      * 8 + (kg ^ tx)];
                b4[ii + 4] = Bs4[buf][(tx * 4 + 32 + ii) * 8 + (kg ^ tx)];
            }
            if (tx == 0) {
                float4 w4 = CwS[buf][kg];
#pragma unroll
                for (int ii = 0; ii < 8; ii++)
                    cd[ii] += a4[ii].x*w4.x + a4[ii].y*w4.y + a4[ii].z*w4.z + a4[ii].w*w4.w;
            }
#pragma unroll
            for (int ii = 0; ii < 8; ii++)
#pragma unroll
                for (int jj = 0; jj < 8; jj++) {
                    acc[ii][jj] += a4[ii].x * b4[jj].x + a4[ii].y * b4[jj].y
                                 + a4[ii].z * b4[jj].z + a4[ii].w * b4[jj].w;
                }
        }
        __syncthreads();
    }

    float* GP = z ? g_G2 : g_G;
#pragma unroll
    for (int ii = 0; ii < 8; ii++) {
        int gi = i0 + ty * 4 + (ii & 3) + ((ii >= 4) ? 32 : 0);
        if (gi < CL_) {
            float* g = GP + ((size_t)(b * CL_ + gi) << 6);
            *(float4*)(g + tx * 4)      = make_float4(acc[ii][0], acc[ii][1], acc[ii][2], acc[ii][3]);
            *(float4*)(g + tx * 4 + 32) = make_float4(acc[ii][4], acc[ii][5], acc[ii][6], acc[ii][7]);
        }
    }
    if (tx == 0) {
        float* CP = z ? g_cdot2 : g_cdot;
#pragma unroll
        for (int ii = 0; ii < 8; ii++) {
            int gi = i0 + ty * 4 + (ii & 3) + ((ii >= 4) ? 32 : 0);
            if (gi < CL_) CP[b * CL_ + gi] = cd[ii];
        }
    }
}

// ============================================================
// K2a: softmax over q dim (warp per (b,i) row); sums split-K partials.
// ============================================================
__global__ __launch_bounds__(256) void k_soft1(
    const int* __restrict__ qmask, const float* __restrict__ bias)
{
    int gw   = (blockIdx.x * 256 + threadIdx.x) >> 5;
    int lane = threadIdx.x & 31;
    if (gw >= B_ * CL_) return;
    int b = gw / CL_;
    float bi = bias[0];
    float cd = g_cdot[gw] + g_cdot2[gw];
    const float* G1 = g_G  + ((size_t)gw << 6);
    const float* G2 = g_G2 + ((size_t)gw << 6);

    int j1 = lane, j2 = lane + 32;
    float v1 = qmask[b * QL_ + j1]
             ? (G1[j1] + G2[j1] + cd + g_qdot[b*QS_ + j1] + bi) : -1e30f;
    float v2 = -1e38f;
    if (j2 < QL_) v2 = qmask[b * QL_ + j2]
             ? (G1[j2] + G2[j2] + cd + g_qdot[b*QS_ + j2] + bi) : -1e30f;

    float mx = fmaxf(v1, v2);
#pragma unroll
    for (int o = 16; o; o >>= 1) mx = fmaxf(mx, __shfl_xor_sync(0xffffffffu, mx, o));
    float e1 = expf(v1 - mx);
    float e2 = (j2 < QL_) ? expf(v2 - mx) : 0.f;
    float s = e1 + e2;
#pragma unroll
    for (int o = 16; o; o >>= 1) s += __shfl_xor_sync(0xffffffffu, s, o);
    float inv = 1.f / s;

    float* s1row = g_s1 + ((size_t)gw << 6);
    s1row[j1] = e1 * inv;
    s1row[j2] = (j2 < QL_) ? e2 * inv : 0.f;
}

// ============================================================
// K2b-A: soft2 phase A. Block (b, z) handles row slab [z*50, (z+1)*50).
// 256 threads = 4 r x 64 j. Online max/sum, partials to g_pM/g_pS.
// ============================================================
__global__ __launch_bounds__(256) void k_s2part(
    const int* __restrict__ cmask, const float* __restrict__ bias)
{
    __shared__ float Ms[4][64], Ss[4][64];
    int blk = blockIdx.x;            // b*8 + z
    int z = blk & 7, b = blk >> 3;
    int j = threadIdx.x & 63;
    int r = threadIdx.x >> 6;        // 0..3
    float qd = g_qdot[b * QS_ + j] + bias[0];

    float m = -1e38f, s = 0.f;
    int i1 = (z + 1) * 50;
    for (int i = z * 50 + r; i < i1; i += 4) {
        size_t off = ((size_t)(b * CL_ + i) << 6) + j;
        float v = g_G[off] + g_G2[off]
                + g_cdot[b * CL_ + i] + g_cdot2[b * CL_ + i] + qd;
        v = cmask[b * CL_ + i] ? v : -1e30f;
        if (v > m) { s = s * expf(m - v) + 1.f; m = v; }
        else       { s += expf(v - m); }
    }
    Ms[r][j] = m; Ss[r][j] = s;
    __syncthreads();
    if (r == 0) {
        float M = Ms[0][j], S = Ss[0][j];
#pragma unroll
        for (int u = 1; u < 4; u++) {
            float m2 = Ms[u][j], s2 = Ss[u][j];
            if (m2 > M) { S = S * expf(M - m2) + s2; M = m2; }
            else        { S += s2 * expf(m2 - M); }
        }
        g_pM[blk * QS_ + j] = M;
        g_pS[blk * QS_ + j] = S;
    }
}

// ============================================================
// K2b-B: soft2 phase B. Same block mapping; combine the 8 slab partials
// (redundantly per block), then write this slab's s2 (pads j>=50 to 0).
// ============================================================
__global__ __launch_bounds__(256) void k_soft2w(
    const int* __restrict__ cmask, const float* __restrict__ bias)
{
    __shared__ float Mf[64], Sf[64];
    int blk = blockIdx.x;            // b*8 + z
    int z = blk & 7, b = blk >> 3;
    int j = threadIdx.x & 63;
    int r = threadIdx.x >> 6;        // 0..3
    float qd = g_qdot[b * QS_ + j] + bias[0];

    if (r == 0) {
        float M = g_pM[(b * 8) * QS_ + j], S = g_pS[(b * 8) * QS_ + j];
#pragma unroll
        for (int u = 1; u < 8; u++) {
            float m2 = g_pM[(b * 8 + u) * QS_ + j];
            float s2 = g_pS[(b * 8 + u) * QS_ + j];
            if (m2 > M) { S = S * expf(M - m2) + s2; M = m2; }
            else        { S += s2 * expf(m2 - M); }
        }
        Mf[j] = M; Sf[j] = 1.f / S;
    }
    __syncthreads();
    float M = Mf[j], invS = Sf[j];

    int i1 = (z + 1) * 50;
    if (j < QL_) {
        for (int i = z * 50 + r; i < i1; i += 4) {
            size_t off = ((size_t)(b * CL_ + i) << 6) + j;
            float v = g_G[off] + g_G2[off]
                    + g_cdot[b * CL_ + i] + g_cdot2[b * CL_ + i] + qd;
            v = cmask[b * CL_ + i] ? v : -1e30f;
            g_s2[off] = expf(v - M) * invS;
        }
    } else {
        for (int i = z * 50 + r; i < i1; i += 4)
            g_s2[((size_t)(b * CL_ + i) << 6) + j] = 0.f;
    }
}

// ============================================================
// K3: t[b, j 64, h-tile 128] = s2^T @ c, K=CL (13 chunks of 32).
// 128 threads, micro 8x8, outer-product, cp.async.
// ============================================================
__global__ __launch_bounds__(128) void k_s2tc(const float* __restrict__ c)
{
    __shared__ float4 As4[2][512];    // [k 32][m-groups 16]
    __shared__ float4 Bs4[2][1024];   // [k 32][n-groups 32]
    int b  = blockIdx.y;
    int h0 = blockIdx.x * 128;
    int tid = threadIdx.x, tx = tid & 15, ty = tid >> 4;

    float acc[8][8];
#pragma unroll
    for (int i = 0; i < 8; i++)
#pragma unroll
        for (int j = 0; j < 8; j++) acc[i][j] = 0.f;

    auto stage = [&](int ch, int buf) {
        int kc = ch * 32;
#pragma unroll
        for (int u = 0; u < 4; u++) {
            int idx = tid + 128 * u;
            int il = idx >> 4, jg = idx & 15;
            bool p = (kc + il) < CL_;
            const float* src = g_s2 + ((size_t)(b * CL_ + (p ? kc + il : 0)) << 6) + jg * 4;
            cp_async16(smem_u32(&As4[buf][il * 16 + (jg ^ ((il >> 2) & 7))]), src, p);
        }
#pragma unroll
        for (int u = 0; u < 8; u++) {
            int idx = tid + 128 * u;
            int il = idx >> 5, hg = idx & 31;
            bool p = (kc + il) < CL_;
            const float* src = c + (size_t)(b * CL_ + (p ? kc + il : 0)) * H_ + h0 + hg * 4;
            cp_async16(smem_u32(&Bs4[buf][il * 32 + (hg ^ ((il >> 2) & 7))]), src, p);
        }
        cp_commit();
    };

    stage(0, 0);
    for (int ch = 0; ch < 13; ch++) {
        int buf = ch & 1;
        if (ch < 12) {
            stage(ch + 1, buf ^ 1);
            asm volatile("cp.async.wait_group 1;" ::: "memory");
        } else {
            asm volatile("cp.async.wait_group 0;" ::: "memory");
        }
        __syncthreads();
#pragma unroll 4
        for (int kk = 0; kk < 32; kk++) {
            int s = (kk >> 2) & 7;
            float4 a0 = As4[buf][kk * 16 + (ty ^ s)];
            float4 a1 = As4[buf][kk * 16 + ((ty + 8) ^ s)];
            float4 b0 = Bs4[buf][kk * 32 + (tx ^ s)];
            float4 b1 = Bs4[buf][kk * 32 + ((tx + 16) ^ s)];
            float av[8] = {a0.x,a0.y,a0.z,a0.w, a1.x,a1.y,a1.z,a1.w};
            float bv[8] = {b0.x,b0.y,b0.z,b0.w, b1.x,b1.y,b1.z,b1.w};
#pragma unroll
            for (int ii = 0; ii < 8; ii++)
#pragma unroll
                for (int jj = 0; jj < 8; jj++) acc[ii][jj] += av[ii] * bv[jj];
        }
        __syncthreads();
    }

#pragma unroll
    for (int ii = 0; ii < 8; ii++) {
        int j = ty * 4 + (ii & 3) + ((ii >= 4) ? 32 : 0);
        float* gt = g_t + (size_t)(b * QS_ + j) * H_ + h0;
        *(float4*)(gt + tx * 4)      = make_float4(acc[ii][0], acc[ii][1], acc[ii][2], acc[ii][3]);
        *(float4*)(gt + tx * 4 + 64) = make_float4(acc[ii][4], acc[ii][5], acc[ii][6], acc[ii][7]);
    }
}

// ============================================================
// K4: a = s1 @ qpad, bb = s1 @ t (K=64 resident), fused epilogue
//     out = [c, a, c*a, c*bb]. 128 threads, dual micro 8x4.
// ============================================================
__global__ __launch_bounds__(128) void k_out(
    const float* __restrict__ c, float* __restrict__ out)
{
    __shared__ float  As[64][64];    // [j][i] swizzled (s1^T)
    __shared__ float4 BQ4[1024];     // [j][h-groups 16]
    __shared__ float4 BT4[1024];
    int b  = blockIdx.z;
    int h0 = blockIdx.y * 64;
    int i0 = blockIdx.x * 64;
    int tid = threadIdx.x, tx = tid & 15, ty = tid >> 4;
    const float* cb = c + (size_t)b * CL_ * H_;

#pragma unroll
    for (int u = 0; u < 8; u++) {
        int idx = tid + 128 * u;
        int il = idx >> 4, jg = idx & 15;
        int gi = i0 + il;
        float4 v = make_float4(0.f, 0.f, 0.f, 0.f);
        if (gi < CL_) v = *(const float4*)(g_s1 + ((size_t)(b * CL_ + gi) << 6) + jg * 4);
        int colb = (((il >> 2) ^ (jg & 7)) << 2) | (il & 3);
        As[jg*4+0][colb] = v.x; As[jg*4+1][colb] = v.y;
        As[jg*4+2][colb] = v.z; As[jg*4+3][colb] = v.w;
    }
#pragma unroll
    for (int u = 0; u < 8; u++) {
        int idx = tid + 128 * u;
        int jl = idx >> 4, hg = idx & 15;
        size_t src = (size_t)(b * QS_ + jl) * H_ + h0 + hg * 4;
        int d = jl * 16 + (hg ^ ((jl >> 2) & 7));
        BQ4[d] = *(const float4*)(g_qpad + src);
        BT4[d] = *(const float4*)(g_t + src);
    }
    __syncthreads();

    float accA[8][4], accB[8][4];
#pragma unroll
    for (int i = 0; i < 8; i++)
#pragma unroll
        for (int j = 0; j < 4; j++) { accA[i][j] = 0.f; accB[i][j] = 0.f; }

#pragma unroll 4
    for (int kk = 0; kk < 64; kk++) {
        int s = (kk >> 2) & 7;
        float4 a0 = *(const float4*)&As[kk][(ty ^ s) << 2];
        float4 a1 = *(const float4*)&As[kk][((ty + 8) ^ s) << 2];
        float4 q  = BQ4[kk * 16 + (tx ^ s)];
        float4 t  = BT4[kk * 16 + (tx ^ s)];
        float av[8] = {a0.x,a0.y,a0.z,a0.w, a1.x,a1.y,a1.z,a1.w};
        float qv[4] = {q.x, q.y, q.z, q.w};
        float tv[4] = {t.x, t.y, t.z, t.w};
#pragma unroll
        for (int ii = 0; ii < 8; ii++)
#pragma unroll
            for (int jj = 0; jj < 4; jj++) {
                accA[ii][jj] += av[ii] * qv[jj];
                accB[ii][jj] += av[ii] * tv[jj];
            }
    }

#pragma unroll
    for (int ii = 0; ii < 8; ii++) {
        int gi = i0 + ty * 4 + (ii & 3) + ((ii >= 4) ? 32 : 0);
        if (gi >= CL_) continue;
        float4 cv = *(const float4*)(cb + (size_t)gi * H_ + h0 + tx * 4);
        float4 av = make_float4(accA[ii][0], accA[ii][1], accA[ii][2], accA[ii][3]);
        float4 bv = make_float4(accB[ii][0], accB[ii][1], accB[ii][2], accB[ii][3]);
        float* o = out + (size_t)(b * CL_ + gi) * (4 * H_) + h0 + tx * 4;
        *(float4*)(o)          = cv;
        *(float4*)(o + H_)     = av;
        *(float4*)(o + 2*H_)   = make_float4(cv.x*av.x, cv.y*av.y, cv.z*av.z, cv.w*av.w);
        *(float4*)(o + 3*H_)   = make_float4(cv.x*bv.x, cv.y*bv.y, cv.z*bv.z, cv.w*bv.w);
    }
}

// ============================================================
extern "C" void kernel_launch(void* const* d_in, const int* in_sizes, int n_in,
                              void* d_out, int out_size)
{
    const float* c    = (const float*)d_in[0];
    const float* q    = (const float*)d_in[1];
    const int*   cmask= (const int*)  d_in[2];
    const int*   qmask= (const int*)  d_in[3];
    const float* cw   = (const float*)d_in[4];
    const float* qw   = (const float*)d_in[5];
    const float* cqw  = (const float*)d_in[6];
    const float* bias = (const float*)d_in[7];
    float* out = (float*)d_out;

    k_qpad   <<<4096, 256>>>(q, cqw, qw);
    k_simgemm<<<dim3(7, B_, 2), 64>>>(c, cw);
    k_soft1  <<<3200, 256>>>(qmask, bias);
    k_s2part <<<B_ * 8, 256>>>(cmask, bias);
    k_soft2w <<<B_ * 8, 256>>>(cmask, bias);
    k_s2tc   <<<dim3(8, B_), 128>>>(c);
    k_out    <<<dim3(7, 16, B_), 128>>>(c, out);
}

// round 12
// speedup vs baseline: 1.0345x; 1.0345x over previous
#include <cuda_runtime.h>
#include <cstdint>

// Attention_18021682774359: BiDAF-style context-query attention.
// B=64, CL=400, QL=50, H=1024. Output [B, CL, 4H] fp32.
//
// Round 12: round-10 config (single-G K1 with fused cdot, qdot in k_qpad,
// cp.async GEMMs) + soft2 re-gridded to B*4 blocks (512 thr = 32r x 16j):
// full-chip occupancy, short online chains, coalesced strips. Split-K dropped
// permanently (two experiments: neutral then regression).

namespace {
constexpr int B_  = 64;
constexpr int CL_ = 400;
constexpr int QL_ = 50;
constexpr int H_  = 1024;
constexpr int QS_ = 64;   // padded QL
}

// -------- scratch (device globals; allocation-free) --------
__device__ float g_G    [B_*CL_*QS_];
__device__ float g_s1   [B_*CL_*QS_];
__device__ float g_s2   [B_*CL_*QS_];
__device__ float g_qpad [B_*QS_*H_];    // raw q, zero-padded rows
__device__ float g_qpadw[B_*QS_*H_];    // q * cqw, zero-padded rows
__device__ float g_t    [B_*QS_*H_];
__device__ float g_cdot [B_*CL_];
__device__ float g_qdot [B_*QS_];

__device__ __forceinline__ unsigned smem_u32(const void* p) {
    return (unsigned)__cvta_generic_to_shared(p);
}
__device__ __forceinline__ void cp_async16(unsigned dst, const void* src, bool pred) {
    int sz = pred ? 16 : 0;
    asm volatile("cp.async.cg.shared.global [%0], [%1], 16, %2;"
                 :: "r"(dst), "l"(src), "r"(sz) : "memory");
}
__device__ __forceinline__ void cp_commit() {
    asm volatile("cp.async.commit_group;" ::: "memory");
}

// ============================================================
// K0: zero-padded q copies + fused qdot (block == one (b,j) row)
// ============================================================
__global__ __launch_bounds__(256) void k_qpad(
    const float* __restrict__ q, const float* __restrict__ cqw,
    const float* __restrict__ qw)
{
    __shared__ float red[8];
    int blk = blockIdx.x;            // b*64 + j
    int j = blk & 63, b = blk >> 6;
    int h4 = threadIdx.x;            // 0..255 float4 position
    float4 v = make_float4(0.f, 0.f, 0.f, 0.f);
    if (j < QL_) v = ((const float4*)q)[((b * QL_ + j) << 8) + h4];
    int idx = (blk << 8) + h4;
    ((float4*)g_qpad)[idx] = v;
    float4 w = ((const float4*)cqw)[h4];
    ((float4*)g_qpadw)[idx] = make_float4(v.x*w.x, v.y*w.y, v.z*w.z, v.w*w.w);

    float4 ww = ((const float4*)qw)[h4];
    float s = v.x*ww.x + v.y*ww.y + v.z*ww.z + v.w*ww.w;
#pragma unroll
    for (int o = 16; o; o >>= 1) s += __shfl_xor_sync(0xffffffffu, s, o);
    int lane = threadIdx.x & 31, wid = threadIdx.x >> 5;
    if (lane == 0) red[wid] = s;
    __syncthreads();
    if (threadIdx.x == 0) {
        float t = 0.f;
#pragma unroll
        for (int r = 0; r < 8; r++) t += red[r];
        g_qdot[blk] = t;
    }
}

// ============================================================
// K1: G[b, i-tile 64, j 64] = c @ qpadw^T, K=1024 (32 chunks of 32).
// 64 threads, micro 8x8, k-vectorized, crosswise swizzle, cp.async.
// Fused: tx==0 lanes accumulate cdot = c . cw from the resident A-tile.
// ============================================================
__global__ __launch_bounds__(64) void k_simgemm(
    const float* __restrict__ c, const float* __restrict__ cw)
{
    __shared__ float4 As4[2][512];   // 64 rows x 8 kgroups
    __shared__ float4 Bs4[2][512];
    __shared__ float4 CwS[2][8];
    int b  = blockIdx.y;
    int i0 = blockIdx.x * 64;
    int tid = threadIdx.x, tx = tid & 7, ty = tid >> 3;
    const float* cb = c        + (size_t)b * CL_ * H_;
    const float* qb = g_qpadw  + (size_t)b * QS_ * H_;

    float acc[8][8];
#pragma unroll
    for (int i = 0; i < 8; i++)
#pragma unroll
        for (int j = 0; j < 8; j++) acc[i][j] = 0.f;
    float cd[8];
#pragma unroll
    for (int i = 0; i < 8; i++) cd[i] = 0.f;

    auto stage = [&](int ch, int buf) {
        int kc = ch * 32;
#pragma unroll
        for (int u = 0; u < 8; u++) {
            int idx = tid + 64 * u;
            int m = idx >> 3, kg = idx & 7;
            bool p = (i0 + m) < CL_;
            const float* src = cb + (size_t)(p ? (i0 + m) : 0) * H_ + kc + kg * 4;
            cp_async16(smem_u32(&As4[buf][m * 8 + (kg ^ ((m >> 2) & 7))]), src, p);
        }
#pragma unroll
        for (int u = 0; u < 8; u++) {
            int idx = tid + 64 * u;
            int n = idx >> 3, kg = idx & 7;
            cp_async16(smem_u32(&Bs4[buf][n * 8 + (kg ^ ((n >> 2) & 7))]),
                       qb + (size_t)n * H_ + kc + kg * 4, true);
        }
        if (tid < 8) cp_async16(smem_u32(&CwS[buf][tid]), cw + kc + tid * 4, true);
        cp_commit();
    };

    stage(0, 0);
    for (int ch = 0; ch < 32; ch++) {
        int buf = ch & 1;
        if (ch < 31) {
            stage(ch + 1, buf ^ 1);
            asm volatile("cp.async.wait_group 1;" ::: "memory");
        } else {
            asm volatile("cp.async.wait_group 0;" ::: "memory");
        }
        __syncthreads();
#pragma unroll 1
        for (int kg = 0; kg < 8; kg++) {
            float4 a4[8], b4[8];
#pragma unroll
            for (int ii = 0; ii < 4; ii++) {
                a4[ii]     = As4[buf][(ty * 4 + ii)      * 8 + (kg ^ ty)];
                a4[ii + 4] = As4[buf][(ty * 4 + 32 + ii) * 8 + (kg ^ ty)];
                b4[ii]     = Bs4[buf][(tx * 4 + ii)      * 8 + (kg ^ tx)];
                b4[ii + 4] = Bs4[buf][(tx * 4 + 32 + ii) * 8 + (kg ^ tx)];
            }
            if (tx == 0) {
                float4 w4 = CwS[buf][kg];
#pragma unroll
                for (int ii = 0; ii < 8; ii++)
                    cd[ii] += a4[ii].x*w4.x + a4[ii].y*w4.y + a4[ii].z*w4.z + a4[ii].w*w4.w;
            }
#pragma unroll
            for (int ii = 0; ii < 8; ii++)
#pragma unroll
                for (int jj = 0; jj < 8; jj++) {
                    acc[ii][jj] += a4[ii].x * b4[jj].x + a4[ii].y * b4[jj].y
                                 + a4[ii].z * b4[jj].z + a4[ii].w * b4[jj].w;
                }
        }
        __syncthreads();
    }

#pragma unroll
    for (int ii = 0; ii < 8; ii++) {
        int gi = i0 + ty * 4 + (ii & 3) + ((ii >= 4) ? 32 : 0);
        if (gi < CL_) {
            float* g = g_G + ((size_t)(b * CL_ + gi) << 6);
            *(float4*)(g + tx * 4)      = make_float4(acc[ii][0], acc[ii][1], acc[ii][2], acc[ii][3]);
            *(float4*)(g + tx * 4 + 32) = make_float4(acc[ii][4], acc[ii][5], acc[ii][6], acc[ii][7]);
        }
    }
    if (tx == 0) {
#pragma unroll
        for (int ii = 0; ii < 8; ii++) {
            int gi = i0 + ty * 4 + (ii & 3) + ((ii >= 4) ? 32 : 0);
            if (gi < CL_) g_cdot[b * CL_ + gi] = cd[ii];
        }
    }
}

// ============================================================
// K2a: softmax over q dim (warp per (b,i) row).
// ============================================================
__global__ __launch_bounds__(256) void k_soft1(
    const int* __restrict__ qmask, const float* __restrict__ bias)
{
    int gw   = (blockIdx.x * 256 + threadIdx.x) >> 5;
    int lane = threadIdx.x & 31;
    if (gw >= B_ * CL_) return;
    int b = gw / CL_;
    float bi = bias[0];
    float cd = g_cdot[gw];
    const float* Grow = g_G + ((size_t)gw << 6);

    int j1 = lane, j2 = lane + 32;
    float v1 = qmask[b * QL_ + j1] ? (Grow[j1] + cd + g_qdot[b*QS_ + j1] + bi) : -1e30f;
    float v2 = -1e38f;
    if (j2 < QL_) v2 = qmask[b * QL_ + j2] ? (Grow[j2] + cd + g_qdot[b*QS_ + j2] + bi) : -1e30f;

    float mx = fmaxf(v1, v2);
#pragma unroll
    for (int o = 16; o; o >>= 1) mx = fmaxf(mx, __shfl_xor_sync(0xffffffffu, mx, o));
    float e1 = expf(v1 - mx);
    float e2 = (j2 < QL_) ? expf(v2 - mx) : 0.f;
    float s = e1 + e2;
#pragma unroll
    for (int o = 16; o; o >>= 1) s += __shfl_xor_sync(0xffffffffu, s, o);
    float inv = 1.f / s;

    float* s1row = g_s1 + ((size_t)gw << 6);
    s1row[j1] = e1 * inv;
    s1row[j2] = (j2 < QL_) ? e2 * inv : 0.f;
}

// ============================================================
// K2b: softmax over c dim. Grid = B*4; block = (b, 16-wide j strip).
// 512 threads = 32 r-slices x 16 j. Online max/sum over rows i = r + 32k,
// smem combine of 32 partials, then coalesced normalize+store pass.
// Pads j >= 50 to zero.
// ============================================================
__global__ __launch_bounds__(512) void k_soft2(
    const int* __restrict__ cmask, const float* __restrict__ bias)
{
    __shared__ float Ms[32][16], Ss[32][16];
    int blk = blockIdx.x;                // b*4 + strip
    int strip = blk & 3, b = blk >> 2;
    int jl = threadIdx.x & 15;
    int j  = strip * 16 + jl;
    int r  = threadIdx.x >> 4;           // 0..31
    float qd = g_qdot[b * QS_ + j] + bias[0];

    float m = -1e38f, s = 0.f;
    for (int i = r; i < CL_; i += 32) {
        float v = g_G[((size_t)(b * CL_ + i) << 6) + j] + g_cdot[b * CL_ + i] + qd;
        v = cmask[b * CL_ + i] ? v : -1e30f;
        if (v > m) { s = s * expf(m - v) + 1.f; m = v; }
        else       { s += expf(v - m); }
    }
    Ms[r][jl] = m; Ss[r][jl] = s;
    __syncthreads();
    if (r == 0) {
        float M = Ms[0][jl], S = Ss[0][jl];
#pragma unroll
        for (int u = 1; u < 32; u++) {
            float m2 = Ms[u][jl], s2 = Ss[u][jl];
            if (m2 > M) { S = S * expf(M - m2) + s2; M = m2; }
            else        { S += s2 * expf(m2 - M); }
        }
        Ms[0][jl] = M; Ss[0][jl] = 1.f / S;
    }
    __syncthreads();
    float M = Ms[0][jl], invS = Ss[0][jl];

    if (j < QL_) {
        for (int i = r; i < CL_; i += 32) {
            float v = g_G[((size_t)(b * CL_ + i) << 6) + j] + g_cdot[b * CL_ + i] + qd;
            v = cmask[b * CL_ + i] ? v : -1e30f;
            g_s2[((size_t)(b * CL_ + i) << 6) + j] = expf(v - M) * invS;
        }
    } else {
        for (int i = r; i < CL_; i += 32)
            g_s2[((size_t)(b * CL_ + i) << 6) + j] = 0.f;
    }
}

// ============================================================
// K3: t[b, j 64, h-tile 128] = s2^T @ c, K=CL (13 chunks of 32).
// 128 threads, micro 8x8, outer-product, cp.async.
// ============================================================
__global__ __launch_bounds__(128) void k_s2tc(const float* __restrict__ c)
{
    __shared__ float4 As4[2][512];    // [k 32][m-groups 16]
    __shared__ float4 Bs4[2][1024];   // [k 32][n-groups 32]
    int b  = blockIdx.y;
    int h0 = blockIdx.x * 128;
    int tid = threadIdx.x, tx = tid & 15, ty = tid >> 4;

    float acc[8][8];
#pragma unroll
    for (int i = 0; i < 8; i++)
#pragma unroll
        for (int j = 0; j < 8; j++) acc[i][j] = 0.f;

    auto stage = [&](int ch, int buf) {
        int kc = ch * 32;
#pragma unroll
        for (int u = 0; u < 4; u++) {
            int idx = tid + 128 * u;
            int il = idx >> 4, jg = idx & 15;
            bool p = (kc + il) < CL_;
            const float* src = g_s2 + ((size_t)(b * CL_ + (p ? kc + il : 0)) << 6) + jg * 4;
            cp_async16(smem_u32(&As4[buf][il * 16 + (jg ^ ((il >> 2) & 7))]), src, p);
        }
#pragma unroll
        for (int u = 0; u < 8; u++) {
            int idx = tid + 128 * u;
            int il = idx >> 5, hg = idx & 31;
            bool p = (kc + il) < CL_;
            const float* src = c + (size_t)(b * CL_ + (p ? kc + il : 0)) * H_ + h0 + hg * 4;
            cp_async16(smem_u32(&Bs4[buf][il * 32 + (hg ^ ((il >> 2) & 7))]), src, p);
        }
        cp_commit();
    };

    stage(0, 0);
    for (int ch = 0; ch < 13; ch++) {
        int buf = ch & 1;
        if (ch < 12) {
            stage(ch + 1, buf ^ 1);
            asm volatile("cp.async.wait_group 1;" ::: "memory");
        } else {
            asm volatile("cp.async.wait_group 0;" ::: "memory");
        }
        __syncthreads();
#pragma unroll 4
        for (int kk = 0; kk < 32; kk++) {
            int s = (kk >> 2) & 7;
            float4 a0 = As4[buf][kk * 16 + (ty ^ s)];
            float4 a1 = As4[buf][kk * 16 + ((ty + 8) ^ s)];
            float4 b0 = Bs4[buf][kk * 32 + (tx ^ s)];
            float4 b1 = Bs4[buf][kk * 32 + ((tx + 16) ^ s)];
            float av[8] = {a0.x,a0.y,a0.z,a0.w, a1.x,a1.y,a1.z,a1.w};
            float bv[8] = {b0.x,b0.y,b0.z,b0.w, b1.x,b1.y,b1.z,b1.w};
#pragma unroll
            for (int ii = 0; ii < 8; ii++)
#pragma unroll
                for (int jj = 0; jj < 8; jj++) acc[ii][jj] += av[ii] * bv[jj];
        }
        __syncthreads();
    }

#pragma unroll
    for (int ii = 0; ii < 8; ii++) {
        int j = ty * 4 + (ii & 3) + ((ii >= 4) ? 32 : 0);
        float* gt = g_t + (size_t)(b * QS_ + j) * H_ + h0;
        *(float4*)(gt + tx * 4)      = make_float4(acc[ii][0], acc[ii][1], acc[ii][2], acc[ii][3]);
        *(float4*)(gt + tx * 4 + 64) = make_float4(acc[ii][4], acc[ii][5], acc[ii][6], acc[ii][7]);
    }
}

// ============================================================
// K4: a = s1 @ qpad, bb = s1 @ t (K=64 resident), fused epilogue
//     out = [c, a, c*a, c*bb]. 128 threads, dual micro 8x4.
// ============================================================
__global__ __launch_bounds__(128) void k_out(
    const float* __restrict__ c, float* __restrict__ out)
{
    __shared__ float  As[64][64];    // [j][i] swizzled (s1^T)
    __shared__ float4 BQ4[1024];     // [j][h-groups 16]
    __shared__ float4 BT4[1024];
    int b  = blockIdx.z;
    int h0 = blockIdx.y * 64;
    int i0 = blockIdx.x * 64;
    int tid = threadIdx.x, tx = tid & 15, ty = tid >> 4;
    const float* cb = c + (size_t)b * CL_ * H_;

#pragma unroll
    for (int u = 0; u < 8; u++) {
        int idx = tid + 128 * u;
        int il = idx >> 4, jg = idx & 15;
        int gi = i0 + il;
        float4 v = make_float4(0.f, 0.f, 0.f, 0.f);
        if (gi < CL_) v = *(const float4*)(g_s1 + ((size_t)(b * CL_ + gi) << 6) + jg * 4);
        int colb = (((il >> 2) ^ (jg & 7)) << 2) | (il & 3);
        As[jg*4+0][colb] = v.x; As[jg*4+1][colb] = v.y;
        As[jg*4+2][colb] = v.z; As[jg*4+3][colb] = v.w;
    }
#pragma unroll
    for (int u = 0; u < 8; u++) {
        int idx = tid + 128 * u;
        int jl = idx >> 4, hg = idx & 15;
        size_t src = (size_t)(b * QS_ + jl) * H_ + h0 + hg * 4;
        int d = jl * 16 + (hg ^ ((jl >> 2) & 7));
        BQ4[d] = *(const float4*)(g_qpad + src);
        BT4[d] = *(const float4*)(g_t + src);
    }
    __syncthreads();

    float accA[8][4], accB[8][4];
#pragma unroll
    for (int i = 0; i < 8; i++)
#pragma unroll
        for (int j = 0; j < 4; j++) { accA[i][j] = 0.f; accB[i][j] = 0.f; }

#pragma unroll 4
    for (int kk = 0; kk < 64; kk++) {
        int s = (kk >> 2) & 7;
        float4 a0 = *(const float4*)&As[kk][(ty ^ s) << 2];
        float4 a1 = *(const float4*)&As[kk][((ty + 8) ^ s) << 2];
        float4 q  = BQ4[kk * 16 + (tx ^ s)];
        float4 t  = BT4[kk * 16 + (tx ^ s)];
        float av[8] = {a0.x,a0.y,a0.z,a0.w, a1.x,a1.y,a1.z,a1.w};
        float qv[4] = {q.x, q.y, q.z, q.w};
        float tv[4] = {t.x, t.y, t.z, t.w};
#pragma unroll
        for (int ii = 0; ii < 8; ii++)
#pragma unroll
            for (int jj = 0; jj < 4; jj++) {
                accA[ii][jj] += av[ii] * qv[jj];
                accB[ii][jj] += av[ii] * tv[jj];
            }
    }

#pragma unroll
    for (int ii = 0; ii < 8; ii++) {
        int gi = i0 + ty * 4 + (ii & 3) + ((ii >= 4) ? 32 : 0);
        if (gi >= CL_) continue;
        float4 cv = *(const float4*)(cb + (size_t)gi * H_ + h0 + tx * 4);
        float4 av = make_float4(accA[ii][0], accA[ii][1], accA[ii][2], accA[ii][3]);
        float4 bv = make_float4(accB[ii][0], accB[ii][1], accB[ii][2], accB[ii][3]);
        float* o = out + (size_t)(b * CL_ + gi) * (4 * H_) + h0 + tx * 4;
        *(float4*)(o)          = cv;
        *(float4*)(o + H_)     = av;
        *(float4*)(o + 2*H_)   = make_float4(cv.x*av.x, cv.y*av.y, cv.z*av.z, cv.w*av.w);
        *(float4*)(o + 3*H_)   = make_float4(cv.x*bv.x, cv.y*bv.y, cv.z*bv.z, cv.w*bv.w);
    }
}

// ============================================================
extern "C" void kernel_launch(void* const* d_in, const int* in_sizes, int n_in,
                              void* d_out, int out_size)
{
    const float* c    = (const float*)d_in[0];
    const float* q    = (const float*)d_in[1];
    const int*   cmask= (const int*)  d_in[2];
    const int*   qmask= (const int*)  d_in[3];
    const float* cw   = (const float*)d_in[4];
    const float* qw   = (const float*)d_in[5];
    const float* cqw  = (const float*)d_in[6];
    const float* bias = (const float*)d_in[7];
    float* out = (float*)d_out;

    k_qpad   <<<4096, 256>>>(q, cqw, qw);
    k_simgemm<<<dim3(7, B_), 64>>>(c, cw);
    k_soft1  <<<3200, 256>>>(qmask, bias);
    k_soft2  <<<B_ * 4, 512>>>(cmask, bias);
    k_s2tc   <<<dim3(8, B_), 128>>>(c);
    k_out    <<<dim3(7, 16, B_), 128>>>(c, out);
}